// round 1
// baseline (speedup 1.0000x reference)
#include <cuda_runtime.h>

// Problem constants
constexpr int C_IN  = 128;
constexpr int C_OUT = 256;
constexpr int HH    = 256;
constexpr int WW    = 256;

// Tiling: each CTA computes 64 output channels x 128 pixels (one half of a row).
constexpr int COUT_TILE = 64;
constexpr int PIX_TILE  = 128;
constexpr int CK        = 4;    // input channels per smem chunk
constexpr int XROW      = 132;  // padded x-row length in smem (need 130)

__global__ __launch_bounds__(256) void conv3x3_f32x2_kernel(
    const float* __restrict__ x,     // [C_IN, H, W]
    const float* __restrict__ wgt,   // [C_OUT, C_IN, 3, 3]
    const float* __restrict__ bias,  // [C_OUT]
    float* __restrict__ out)         // [C_OUT, H, W]
{
    __shared__ float xs[CK][3][XROW];          // 3 input rows per channel
    __shared__ float ws[CK][9][COUT_TILE];     // tap-major, cout minor (pairs contiguous)

    const int tid  = threadIdx.x;
    const int warp = tid >> 5;
    const int lane = tid & 31;

    const int x0  = blockIdx.x * PIX_TILE;     // pixel (column) base
    const int y   = blockIdx.y;                // output row
    const int co0 = blockIdx.z * COUT_TILE;    // cout base

    const int px = lane * 4;                   // 4 consecutive pixels per thread
    const int ob = warp * 8;                   // 8 couts per thread (4 pairs)

    // acc[cout_pair][pixel] : f32x2 packed (lanes = cout o, o+1)
    unsigned long long acc[4][4];
    #pragma unroll
    for (int i = 0; i < 4; i++)
        #pragma unroll
        for (int p = 0; p < 4; p++) acc[i][p] = 0ULL;

    for (int c0 = 0; c0 < C_IN; c0 += CK) {
        __syncthreads();

        // ---- load x tile: CK channels x 3 rows x 130 cols (with zero pad) ----
        for (int i = tid; i < CK * 3 * 130; i += 256) {
            int cc  = i / 390;
            int r   = (i % 390) / 130;
            int col = i % 130;
            int gy = y + r - 1;
            int gx = x0 + col - 1;
            float v = 0.0f;
            if ((unsigned)gy < (unsigned)HH && (unsigned)gx < (unsigned)WW)
                v = x[((c0 + cc) * HH + gy) * WW + gx];
            xs[cc][r][col] = v;
        }

        // ---- load weight tile: CK channels x 9 taps x 64 couts ----
        for (int i = tid; i < CK * 9 * COUT_TILE; i += 256) {
            int cc  = i / (9 * COUT_TILE);
            int rem = i % (9 * COUT_TILE);
            int j   = rem / COUT_TILE;
            int o   = rem % COUT_TILE;
            ws[cc][j][o] = wgt[((co0 + o) * C_IN + (c0 + cc)) * 9 + j];
        }
        __syncthreads();

        // ---- compute ----
        #pragma unroll
        for (int cc = 0; cc < CK; cc++) {
            #pragma unroll
            for (int kh = 0; kh < 3; kh++) {
                // 6 x-values cover pixels p+kw for p in [0,4), kw in [0,3)
                unsigned long long xp[6];
                #pragma unroll
                for (int j = 0; j < 6; j++) {
                    float v = xs[cc][kh][px + j];
                    asm("mov.b64 %0, {%1, %1};" : "=l"(xp[j]) : "f"(v));
                }
                #pragma unroll
                for (int kw = 0; kw < 3; kw++) {
                    const int j = kh * 3 + kw;
                    #pragma unroll
                    for (int op = 0; op < 4; op++) {
                        // weight pair (o, o+1): contiguous, 8B aligned, warp-uniform (LDS.64 broadcast)
                        unsigned long long w2 =
                            *reinterpret_cast<const unsigned long long*>(&ws[cc][j][ob + 2 * op]);
                        #pragma unroll
                        for (int p = 0; p < 4; p++) {
                            asm("fma.rn.f32x2 %0, %1, %2, %0;"
                                : "+l"(acc[op][p])
                                : "l"(w2), "l"(xp[kw + p]));
                        }
                    }
                }
            }
        }
    }

    // ---- epilogue: unpack, add bias, vectorized store (float4 over 4 pixels) ----
    const long row_base = (long)y * WW + x0 + px;
    #pragma unroll
    for (int op = 0; op < 4; op++) {
        const int o0 = co0 + ob + 2 * op;
        const float b0 = bias[o0];
        const float b1 = bias[o0 + 1];
        float lo[4], hi[4];
        #pragma unroll
        for (int p = 0; p < 4; p++) {
            asm("mov.b64 {%0, %1}, %2;" : "=f"(lo[p]), "=f"(hi[p]) : "l"(acc[op][p]));
        }
        float4 vlo = make_float4(lo[0] + b0, lo[1] + b0, lo[2] + b0, lo[3] + b0);
        float4 vhi = make_float4(hi[0] + b1, hi[1] + b1, hi[2] + b1, hi[3] + b1);
        *reinterpret_cast<float4*>(&out[(long)o0 * HH * WW + row_base])       = vlo;
        *reinterpret_cast<float4*>(&out[(long)(o0 + 1) * HH * WW + row_base]) = vhi;
    }
}

extern "C" void kernel_launch(void* const* d_in, const int* in_sizes, int n_in,
                              void* d_out, int out_size) {
    const float* x    = (const float*)d_in[0];
    const float* wgt  = (const float*)d_in[1];
    const float* bias = (const float*)d_in[2];
    float* out        = (float*)d_out;

    dim3 grid(WW / PIX_TILE, HH, C_OUT / COUT_TILE);  // (2, 256, 4) = 2048 CTAs
    conv3x3_f32x2_kernel<<<grid, 256>>>(x, wgt, bias, out);
}

// round 3
// speedup vs baseline: 3.9833x; 3.9833x over previous
#include <cuda_runtime.h>
#include <cuda_fp16.h>

#define HH   256
#define WW   256
#define C_IN 128
#define C_OUT 256
#define KTOT 1152

// ---------------- device scratch (static, no allocation) ----------------
__device__ __half g_Xh[(size_t)HH * WW * C_IN];   // [y][x][ci] fp16 hi
__device__ __half g_Xl[(size_t)HH * WW * C_IN];   // [y][x][ci] fp16 lo
__device__ __half g_Wh[C_OUT * KTOT];             // [co][kh][cic][kw][ci32]
__device__ __half g_Wl[C_OUT * KTOT];

// ---------------- helpers ----------------
__device__ __forceinline__ void cpasync16(void* dst_smem, const void* src_gmem) {
    unsigned d = (unsigned)__cvta_generic_to_shared(dst_smem);
    asm volatile("cp.async.cg.shared.global [%0], [%1], 16;"
                 :: "r"(d), "l"(__cvta_generic_to_global(src_gmem)) : "memory");
}
__device__ __forceinline__ void sts_zero16(void* dst_smem) {
    unsigned d = (unsigned)__cvta_generic_to_shared(dst_smem);
    asm volatile("st.shared.v4.b32 [%0], {%1,%1,%1,%1};" :: "r"(d), "r"(0) : "memory");
}
__device__ __forceinline__ void mma16816(float* d, const unsigned* a, const unsigned* b) {
    asm volatile("mma.sync.aligned.m16n8k16.row.col.f32.f16.f16.f32 "
                 "{%0,%1,%2,%3}, {%4,%5,%6,%7}, {%8,%9}, {%0,%1,%2,%3};"
                 : "+f"(d[0]), "+f"(d[1]), "+f"(d[2]), "+f"(d[3])
                 : "r"(a[0]), "r"(a[1]), "r"(a[2]), "r"(a[3]), "r"(b[0]), "r"(b[1]));
}

// ================= prep 1: X -> channel-last fp16 hi/lo =================
#define XP_STRIDE 132   // fp16 per smem row (264B)
__global__ __launch_bounds__(256) void xprep_kernel(const float* __restrict__ x) {
    extern __shared__ char sm[];
    __half* shh = (__half*)sm;                             // [256 xx][XP_STRIDE]
    __half* shl = (__half*)(sm + 256 * XP_STRIDE * 2);

    const int y = blockIdx.x, tid = threadIdx.x, wid = tid >> 5, lane = tid & 31;

    for (int it = 0; it < 16; it++) {
        int ci = wid + it * 8;
        const float* row = x + ((size_t)ci * HH + y) * WW;
        #pragma unroll
        for (int h = 0; h < 2; h++) {
            int xx0 = (lane + h * 32) * 4;
            float4 v = *(const float4*)(row + xx0);
            float vv[4] = {v.x, v.y, v.z, v.w};
            #pragma unroll
            for (int j = 0; j < 4; j++) {
                __half hi = __float2half_rn(vv[j]);
                __half lo = __float2half_rn(vv[j] - __half2float(hi));
                shh[(xx0 + j) * XP_STRIDE + ci] = hi;
                shl[(xx0 + j) * XP_STRIDE + ci] = lo;
            }
        }
    }
    __syncthreads();
    for (int it = 0; it < 32; it++) {
        int xx = wid + it * 8;
        uint2 vh = *(uint2*)&shh[xx * XP_STRIDE + lane * 4];
        uint2 vl = *(uint2*)&shl[xx * XP_STRIDE + lane * 4];
        size_t o = ((size_t)(y * WW + xx) * C_IN + lane * 4);
        *(uint2*)&g_Xh[o] = vh;
        *(uint2*)&g_Xl[o] = vl;
    }
}

// ================= prep 2: W reorder + fp16 hi/lo =================
// dest k' order: kh(3) x cic(4) x kw(3) x ci32(32); src w[co][ci][kh][kw]
__global__ void wprep_kernel(const float* __restrict__ w) {
    int co = blockIdx.x;
    for (int k = threadIdx.x; k < KTOT; k += blockDim.x) {
        int kh = k / 384, r0 = k % 384;
        int cic = r0 / 96, r1 = r0 % 96;
        int kw = r1 / 32, ci5 = r1 % 32;
        int ci = cic * 32 + ci5;
        float v = w[co * KTOT + ci * 9 + kh * 3 + kw];
        __half hi = __float2half_rn(v);
        g_Wh[co * KTOT + k] = hi;
        g_Wl[co * KTOT + k] = __float2half_rn(v - __half2float(hi));
    }
}

// ================= main: implicit GEMM (mma.sync f16, 3 chains) =================
// CTA: 128 cout x 128 px. smem: xT[130 cols][40 fp16] hi/lo + ws[128co][104 fp16] hi/lo
#define XT_STRIDE 40    // fp16 (80B)  -> conflict-free B-frag reads
#define WS_STRIDE 104   // fp16 (208B) -> conflict-free A-frag reads
#define SM_XH 0
#define SM_XL 10400
#define SM_WH 20800
#define SM_WL 47424
#define SM_TOTAL 74048

__global__ __launch_bounds__(256, 2) void conv_mma_kernel(
    const float* __restrict__ bias, float* __restrict__ out)
{
    extern __shared__ char sm[];
    __half* xsh = (__half*)(sm + SM_XH);
    __half* xsl = (__half*)(sm + SM_XL);
    __half* wsh = (__half*)(sm + SM_WH);
    __half* wsl = (__half*)(sm + SM_WL);

    const int tid = threadIdx.x, wid = tid >> 5, lane = tid & 31;
    const int g = lane >> 2, r = lane & 3;
    const int x0 = blockIdx.x * 128;
    const int y  = blockIdx.y;
    const int coH = blockIdx.z;
    const int warp_co = (wid & 3) * 32;
    const int warp_px = (wid >> 2) * 64;

    float d[2][8][4];
    #pragma unroll
    for (int mt = 0; mt < 2; mt++)
        #pragma unroll
        for (int nt = 0; nt < 8; nt++)
            #pragma unroll
            for (int q = 0; q < 4; q++) d[mt][nt][q] = 0.0f;

    for (int kh = 0; kh < 3; kh++) {
        const int yy = y + kh - 1;
        const bool yv = (unsigned)yy < (unsigned)HH;
        for (int cic = 0; cic < 4; cic++) {
            __syncthreads();   // protect smem from prior chunk's readers

            // ---- x chunk: 130 cols x 32 ci (4x 8-ci groups), hi+lo ----
            for (int i = tid; i < 520; i += 256) {
                int col = i >> 2, gi = i & 3;
                int gx = x0 + col - 1;
                __half* dh = xsh + col * XT_STRIDE + gi * 8;
                __half* dl = xsl + col * XT_STRIDE + gi * 8;
                if (yv && (unsigned)gx < (unsigned)WW) {
                    size_t o = ((size_t)(yy * WW + gx) * C_IN + cic * 32 + gi * 8);
                    cpasync16(dh, g_Xh + o);
                    cpasync16(dl, g_Xl + o);
                } else {
                    sts_zero16(dh);
                    sts_zero16(dl);
                }
            }
            // ---- w chunk: 128 co x 96 k (12x 8-half groups), hi+lo ----
            for (int i = tid; i < 1536; i += 256) {
                int co = i / 12, gi = i % 12;
                size_t o = (size_t)(coH * 128 + co) * KTOT + (kh * 4 + cic) * 96 + gi * 8;
                cpasync16(wsh + co * WS_STRIDE + gi * 8, g_Wh + o);
                cpasync16(wsl + co * WS_STRIDE + gi * 8, g_Wl + o);
            }
            asm volatile("cp.async.commit_group;" ::: "memory");
            asm volatile("cp.async.wait_group 0;" ::: "memory");
            __syncthreads();

            // ---- compute: kw(3) x k16(2) steps ----
            #pragma unroll
            for (int kw = 0; kw < 3; kw++) {
                #pragma unroll
                for (int ks = 0; ks < 2; ks++) {
                    const int kb = kw * 32 + ks * 16;
                    unsigned ah[2][4], al[2][4];
                    #pragma unroll
                    for (int mt = 0; mt < 2; mt++) {
                        int rowA = warp_co + mt * 16 + g;
                        const __half* ph = wsh + rowA * WS_STRIDE + kb + 2 * r;
                        const __half* pl = wsl + rowA * WS_STRIDE + kb + 2 * r;
                        ah[mt][0] = *(const unsigned*)(ph);
                        ah[mt][1] = *(const unsigned*)(ph + 8 * WS_STRIDE);
                        ah[mt][2] = *(const unsigned*)(ph + 8);
                        ah[mt][3] = *(const unsigned*)(ph + 8 * WS_STRIDE + 8);
                        al[mt][0] = *(const unsigned*)(pl);
                        al[mt][1] = *(const unsigned*)(pl + 8 * WS_STRIDE);
                        al[mt][2] = *(const unsigned*)(pl + 8);
                        al[mt][3] = *(const unsigned*)(pl + 8 * WS_STRIDE + 8);
                    }
                    #pragma unroll
                    for (int nt = 0; nt < 8; nt++) {
                        int col = warp_px + nt * 8 + g + kw;
                        unsigned bh[2], bl[2];
                        const __half* pbh = xsh + col * XT_STRIDE + ks * 16 + 2 * r;
                        const __half* pbl = xsl + col * XT_STRIDE + ks * 16 + 2 * r;
                        bh[0] = *(const unsigned*)(pbh);
                        bh[1] = *(const unsigned*)(pbh + 8);
                        bl[0] = *(const unsigned*)(pbl);
                        bl[1] = *(const unsigned*)(pbl + 8);
                        mma16816(d[0][nt], ah[0], bh);
                        mma16816(d[1][nt], ah[1], bh);
                        mma16816(d[0][nt], ah[0], bl);
                        mma16816(d[1][nt], ah[1], bl);
                        mma16816(d[0][nt], al[0], bh);
                        mma16816(d[1][nt], al[1], bh);
                    }
                }
            }
        }
    }

    // ---- epilogue: bias + store (float2 per d-pair) ----
    #pragma unroll
    for (int mt = 0; mt < 2; mt++) {
        int co0 = coH * 128 + warp_co + mt * 16 + g;
        int co1 = co0 + 8;
        float b0 = bias[co0], b1 = bias[co1];
        float* row0 = out + (size_t)co0 * (HH * WW) + y * WW + x0;
        float* row1 = out + (size_t)co1 * (HH * WW) + y * WW + x0;
        #pragma unroll
        for (int nt = 0; nt < 8; nt++) {
            int px = warp_px + nt * 8 + 2 * r;
            float2 v0 = make_float2(d[mt][nt][0] + b0, d[mt][nt][1] + b0);
            float2 v1 = make_float2(d[mt][nt][2] + b1, d[mt][nt][3] + b1);
            *(float2*)(row0 + px) = v0;
            *(float2*)(row1 + px) = v1;
        }
    }
}

// ================= launcher =================
extern "C" void kernel_launch(void* const* d_in, const int* in_sizes, int n_in,
                              void* d_out, int out_size) {
    const float* x    = (const float*)d_in[0];
    const float* w    = (const float*)d_in[1];
    const float* bias = (const float*)d_in[2];
    float* out        = (float*)d_out;

    const int xprep_smem = 256 * XP_STRIDE * 2 * 2;  // 135168
    cudaFuncSetAttribute(xprep_kernel, cudaFuncAttributeMaxDynamicSharedMemorySize, xprep_smem);
    cudaFuncSetAttribute(conv_mma_kernel, cudaFuncAttributeMaxDynamicSharedMemorySize, SM_TOTAL);

    xprep_kernel<<<HH, 256, xprep_smem>>>(x);
    wprep_kernel<<<C_OUT, 128>>>(w);
    conv_mma_kernel<<<dim3(2, HH, 2), 256, SM_TOTAL>>>(bias, out);
}

// round 4
// speedup vs baseline: 4.9820x; 1.2507x over previous
#include <cuda_runtime.h>
#include <cuda_fp16.h>

#define HH    256
#define WW    256
#define C_IN  128
#define C_OUT 256
#define KTOT  1152

// ---------------- device scratch (static, no allocation) ----------------
__device__ __half g_Xh[(size_t)HH * WW * C_IN];   // [y][x][ci] fp16 (hi)
__device__ __half g_Wh[C_OUT * KTOT];             // [co][kh][cic][kw][ci32] hi
__device__ __half g_Wl[C_OUT * KTOT];             // lo residual

// ---------------- helpers ----------------
__device__ __forceinline__ void cpasync16(void* dst_smem, const void* src_gmem) {
    unsigned d = (unsigned)__cvta_generic_to_shared(dst_smem);
    asm volatile("cp.async.cg.shared.global [%0], [%1], 16;"
                 :: "r"(d), "l"(__cvta_generic_to_global(src_gmem)) : "memory");
}
__device__ __forceinline__ void sts_zero16(void* dst_smem) {
    unsigned d = (unsigned)__cvta_generic_to_shared(dst_smem);
    asm volatile("st.shared.v4.b32 [%0], {%1,%1,%1,%1};" :: "r"(d), "r"(0) : "memory");
}
#define CP_COMMIT() asm volatile("cp.async.commit_group;" ::: "memory")
#define CP_WAIT(N)  asm volatile("cp.async.wait_group %0;" :: "n"(N) : "memory")

__device__ __forceinline__ void mma16816(float* d, const unsigned* a, const unsigned* b) {
    asm volatile("mma.sync.aligned.m16n8k16.row.col.f32.f16.f16.f32 "
                 "{%0,%1,%2,%3}, {%4,%5,%6,%7}, {%8,%9}, {%0,%1,%2,%3};"
                 : "+f"(d[0]), "+f"(d[1]), "+f"(d[2]), "+f"(d[3])
                 : "r"(a[0]), "r"(a[1]), "r"(a[2]), "r"(a[3]), "r"(b[0]), "r"(b[1]));
}

// ================= prep 1: X -> channel-last fp16 (hi only) =================
#define XP_STRIDE 136   // halves per smem row (272B, 16B-aligned)
__global__ __launch_bounds__(256) void xprep_kernel(const float* __restrict__ x) {
    __shared__ __half sh[128 * XP_STRIDE];   // [128 x][ci]

    const int xh  = blockIdx.x;               // 0/1: which 128-px half
    const int y   = blockIdx.y;
    const int tid = threadIdx.x, wid = tid >> 5, lane = tid & 31;
    const int xbase = xh * 128;

    #pragma unroll
    for (int it = 0; it < 16; it++) {
        const int ci = wid + it * 8;
        float4 v = *(const float4*)(x + ((size_t)ci * HH + y) * WW + xbase + lane * 4);
        const float vv[4] = {v.x, v.y, v.z, v.w};
        #pragma unroll
        for (int j = 0; j < 4; j++)
            sh[(lane * 4 + j) * XP_STRIDE + ci] = __float2half_rn(vv[j]);
    }
    __syncthreads();

    // write out: 128 rows x 256B, coalesced uint4
    #pragma unroll
    for (int p = 0; p < 8; p++) {
        int idx = p * 256 + tid;
        int row = idx >> 4, c = idx & 15;
        uint4 v = *(const uint4*)&sh[row * XP_STRIDE + c * 8];
        *(uint4*)&g_Xh[((size_t)(y * WW + xbase + row)) * C_IN + c * 8] = v;
    }
}

// ================= prep 2: W reorder + fp16 hi/lo =================
// dest k' order: kh(3) x cic(4) x kw(3) x ci32(32); src w[co][ci][kh][kw]
__global__ void wprep_kernel(const float* __restrict__ w) {
    int co = blockIdx.x;
    for (int k = threadIdx.x; k < KTOT; k += blockDim.x) {
        int kh = k / 384, r0 = k % 384;
        int cic = r0 / 96, r1 = r0 % 96;
        int kw = r1 / 32, ci5 = r1 % 32;
        int ci = cic * 32 + ci5;
        float v = w[co * KTOT + ci * 9 + kh * 3 + kw];
        __half hi = __float2half_rn(v);
        g_Wh[co * KTOT + k] = hi;
        g_Wl[co * KTOT + k] = __float2half_rn(v - __half2float(hi));
    }
}

// ================= main: implicit GEMM, 2 chains, 2-stage pipeline =================
#define XT_STRIDE 40    // halves (80B)
#define WS_STRIDE 104   // halves (208B) -> conflict-free LDS
#define OFF_X  0
#define OFF_WH 10400
#define OFF_WL 37024
#define STAGE  63648
#define SM_TOTAL (2 * STAGE)   // 127296

__global__ __launch_bounds__(256, 1) void conv_mma_kernel(
    const float* __restrict__ bias, float* __restrict__ out)
{
    extern __shared__ char sm[];

    const int tid = threadIdx.x, wid = tid >> 5, lane = tid & 31;
    const int g = lane >> 2, r = lane & 3;
    const int x0  = blockIdx.x * 128;
    const int y   = blockIdx.y;
    const int coH = blockIdx.z;
    const int warp_co = (wid & 3) * 32;
    const int warp_px = (wid >> 2) * 64;

    float d[2][8][4];
    #pragma unroll
    for (int mt = 0; mt < 2; mt++)
        #pragma unroll
        for (int nt = 0; nt < 8; nt++)
            #pragma unroll
            for (int q = 0; q < 4; q++) d[mt][nt][q] = 0.0f;

    // ---- chunk loader: chunk c = (kh, cic); fills one stage, commits a group ----
    auto load_chunk = [&](int c, char* st) {
        const int kh = c >> 2, cic = c & 3;
        const int yy = y + kh - 1;
        const bool yv = (unsigned)yy < (unsigned)HH;
        __half* xs = (__half*)(st + OFF_X);
        __half* wh = (__half*)(st + OFF_WH);
        __half* wl = (__half*)(st + OFF_WL);

        // x tile: 130 cols x 32 ci (4 groups of 8 halves)
        #pragma unroll
        for (int i0 = 0; i0 < 3; i0++) {
            int i = tid + i0 * 256;
            if (i < 520) {
                int col = i >> 2, gi = i & 3;
                int gx = x0 + col - 1;
                __half* dst = xs + col * XT_STRIDE + gi * 8;
                if (yv && (unsigned)gx < (unsigned)WW)
                    cpasync16(dst, g_Xh + ((size_t)(yy * WW + gx) * C_IN + cic * 32 + gi * 8));
                else
                    sts_zero16(dst);
            }
        }
        // w tiles: 128 co x 96 halves, hi+lo
        #pragma unroll
        for (int i0 = 0; i0 < 6; i0++) {
            int i = tid + i0 * 256;
            int co = i / 12, gi = i % 12;
            size_t o = (size_t)(coH * 128 + co) * KTOT + (kh * 4 + cic) * 96 + gi * 8;
            cpasync16(wh + co * WS_STRIDE + gi * 8, g_Wh + o);
            cpasync16(wl + co * WS_STRIDE + gi * 8, g_Wl + o);
        }
        CP_COMMIT();
    };

    load_chunk(0, sm);

    for (int c = 0; c < 12; c++) {
        char* cur = sm + (c & 1) * STAGE;
        if (c < 11) {
            load_chunk(c + 1, sm + ((c + 1) & 1) * STAGE);
            CP_WAIT(1);
        } else {
            CP_WAIT(0);
        }
        __syncthreads();

        const __half* xs = (const __half*)(cur + OFF_X);
        const __half* wh = (const __half*)(cur + OFF_WH);
        const __half* wl = (const __half*)(cur + OFF_WL);

        #pragma unroll
        for (int kw = 0; kw < 3; kw++) {
            #pragma unroll
            for (int ks = 0; ks < 2; ks++) {
                const int kb = kw * 32 + ks * 16;
                unsigned ah[2][4], al[2][4];
                #pragma unroll
                for (int mt = 0; mt < 2; mt++) {
                    int rowA = warp_co + mt * 16 + g;
                    const __half* ph = wh + rowA * WS_STRIDE + kb + 2 * r;
                    const __half* pl = wl + rowA * WS_STRIDE + kb + 2 * r;
                    ah[mt][0] = *(const unsigned*)(ph);
                    ah[mt][1] = *(const unsigned*)(ph + 8 * WS_STRIDE);
                    ah[mt][2] = *(const unsigned*)(ph + 8);
                    ah[mt][3] = *(const unsigned*)(ph + 8 * WS_STRIDE + 8);
                    al[mt][0] = *(const unsigned*)(pl);
                    al[mt][1] = *(const unsigned*)(pl + 8 * WS_STRIDE);
                    al[mt][2] = *(const unsigned*)(pl + 8);
                    al[mt][3] = *(const unsigned*)(pl + 8 * WS_STRIDE + 8);
                }
                #pragma unroll
                for (int nt = 0; nt < 8; nt++) {
                    int col = warp_px + nt * 8 + g + kw;
                    const __half* pb = xs + col * XT_STRIDE + ks * 16 + 2 * r;
                    unsigned b[2];
                    b[0] = *(const unsigned*)(pb);
                    b[1] = *(const unsigned*)(pb + 8);
                    mma16816(d[0][nt], ah[0], b);
                    mma16816(d[1][nt], ah[1], b);
                    mma16816(d[0][nt], al[0], b);
                    mma16816(d[1][nt], al[1], b);
                }
            }
        }
        __syncthreads();   // all warps done with `cur` before it is refilled
    }

    // ---- epilogue: bias + float2 stores ----
    #pragma unroll
    for (int mt = 0; mt < 2; mt++) {
        int co0 = coH * 128 + warp_co + mt * 16 + g;
        int co1 = co0 + 8;
        float b0 = bias[co0], b1 = bias[co1];
        float* row0 = out + (size_t)co0 * (HH * WW) + y * WW + x0;
        float* row1 = out + (size_t)co1 * (HH * WW) + y * WW + x0;
        #pragma unroll
        for (int nt = 0; nt < 8; nt++) {
            int px = warp_px + nt * 8 + 2 * r;
            *(float2*)(row0 + px) = make_float2(d[mt][nt][0] + b0, d[mt][nt][1] + b0);
            *(float2*)(row1 + px) = make_float2(d[mt][nt][2] + b1, d[mt][nt][3] + b1);
        }
    }
}

// ================= launcher =================
extern "C" void kernel_launch(void* const* d_in, const int* in_sizes, int n_in,
                              void* d_out, int out_size) {
    const float* x    = (const float*)d_in[0];
    const float* w    = (const float*)d_in[1];
    const float* bias = (const float*)d_in[2];
    float* out        = (float*)d_out;

    cudaFuncSetAttribute(conv_mma_kernel, cudaFuncAttributeMaxDynamicSharedMemorySize, SM_TOTAL);

    xprep_kernel<<<dim3(2, HH), 256>>>(x);
    wprep_kernel<<<C_OUT, 128>>>(w);
    conv_mma_kernel<<<dim3(2, HH, 2), 256, SM_TOTAL>>>(bias, out);
}

// round 5
// speedup vs baseline: 9.5302x; 1.9129x over previous
#include <cuda_runtime.h>
#include <cuda_fp16.h>

#define HH    256
#define WW    256
#define C_IN  128
#define C_OUT 256
#define KTOT  1152

// ---------------- device scratch (static, no allocation) ----------------
__device__ __half g_Xh[(size_t)HH * WW * C_IN];   // [y][x][ci] fp16
__device__ __half g_Wh[C_OUT * KTOT];             // [co][kh][cic][kw][ci32] fp16

// ---------------- helpers ----------------
__device__ __forceinline__ void cpasync16(void* dst_smem, const void* src_gmem) {
    unsigned d = (unsigned)__cvta_generic_to_shared(dst_smem);
    asm volatile("cp.async.cg.shared.global [%0], [%1], 16;"
                 :: "r"(d), "l"(__cvta_generic_to_global(src_gmem)) : "memory");
}
__device__ __forceinline__ void sts_zero16(void* dst_smem) {
    unsigned d = (unsigned)__cvta_generic_to_shared(dst_smem);
    asm volatile("st.shared.v4.b32 [%0], {%1,%1,%1,%1};" :: "r"(d), "r"(0) : "memory");
}
#define CP_COMMIT() asm volatile("cp.async.commit_group;" ::: "memory")
#define CP_WAIT(N)  asm volatile("cp.async.wait_group %0;" :: "n"(N) : "memory")

__device__ __forceinline__ void mma16816(float* d, const unsigned* a, const unsigned* b) {
    asm volatile("mma.sync.aligned.m16n8k16.row.col.f32.f16.f16.f32 "
                 "{%0,%1,%2,%3}, {%4,%5,%6,%7}, {%8,%9}, {%0,%1,%2,%3};"
                 : "+f"(d[0]), "+f"(d[1]), "+f"(d[2]), "+f"(d[3])
                 : "r"(a[0]), "r"(a[1]), "r"(a[2]), "r"(a[3]), "r"(b[0]), "r"(b[1]));
}

// ================= prep 1: X -> channel-last fp16, conflict-free transpose =================
#define XP_STRIDE 130   // halves per x-row (65 words: odd -> conflict-free STS)
__global__ __launch_bounds__(256) void xprep_kernel(const float* __restrict__ x) {
    __shared__ __half sh[128 * XP_STRIDE];   // [x 128][ci 128]

    const int xh  = blockIdx.x;               // which 128-px half of the row
    const int y   = blockIdx.y;
    const int tid = threadIdx.x, wid = tid >> 5, lane = tid & 31;
    const int xbase = xh * 128;

    #pragma unroll
    for (int it = 0; it < 16; it++) {
        const int ci = wid + it * 8;
        const float* row = x + ((size_t)ci * HH + y) * WW + xbase;
        #pragma unroll
        for (int j = 0; j < 4; j++) {
            int xx = j * 32 + lane;                       // coalesced 128B load
            sh[xx * XP_STRIDE + ci] = __float2half_rn(row[xx]);  // stride 65 words: no conflict
        }
    }
    __syncthreads();

    // write out: 128 rows x 256B, coalesced 16B stores (smem reads via 4x b32, 2-way max)
    #pragma unroll
    for (int p = 0; p < 8; p++) {
        int idx = p * 256 + tid;
        int row = idx >> 4, c = idx & 15;
        const unsigned* s = (const unsigned*)&sh[row * XP_STRIDE + c * 8];
        uint4 v = make_uint4(s[0], s[1], s[2], s[3]);
        *(uint4*)&g_Xh[((size_t)(y * WW + xbase + row)) * C_IN + c * 8] = v;
    }
}

// ================= prep 2: W reorder to fp16 =================
// dest k' order: kh(3) x cic(4) x kw(3) x ci32(32); src w[co][ci][kh][kw]
__global__ void wprep_kernel(const float* __restrict__ w) {
    int co = blockIdx.x;
    for (int k = threadIdx.x; k < KTOT; k += blockDim.x) {
        int kh = k / 384, r0 = k % 384;
        int cic = r0 / 96, r1 = r0 % 96;
        int kw = r1 / 32, ci5 = r1 % 32;
        int ci = cic * 32 + ci5;
        g_Wh[co * KTOT + k] = __float2half_rn(w[co * KTOT + ci * 9 + kh * 3 + kw]);
    }
}

// ================= main: implicit GEMM, 1 chain, 2-stage pipeline, 2 CTA/SM =================
#define XT_STRIDE 40    // halves (80B)
#define WS_STRIDE 104   // halves (208B) -> conflict-free LDS
#define OFF_X  0
#define OFF_WH 10400
#define STAGE  37024
#define SM_TOTAL (2 * STAGE)   // 74048

__global__ __launch_bounds__(256, 2) void conv_mma_kernel(
    const float* __restrict__ bias, float* __restrict__ out)
{
    extern __shared__ char sm[];

    const int tid = threadIdx.x, wid = tid >> 5, lane = tid & 31;
    const int g = lane >> 2, r = lane & 3;
    const int x0  = blockIdx.x * 128;
    const int y   = blockIdx.y;
    const int coH = blockIdx.z;
    const int warp_co = (wid & 3) * 32;
    const int warp_px = (wid >> 2) * 64;

    float d[2][8][4];
    #pragma unroll
    for (int mt = 0; mt < 2; mt++)
        #pragma unroll
        for (int nt = 0; nt < 8; nt++)
            #pragma unroll
            for (int q = 0; q < 4; q++) d[mt][nt][q] = 0.0f;

    // ---- chunk loader: chunk c = (kh, cic) ----
    auto load_chunk = [&](int c, char* st) {
        const int kh = c >> 2, cic = c & 3;
        const int yy = y + kh - 1;
        const bool yv = (unsigned)yy < (unsigned)HH;
        __half* xs = (__half*)(st + OFF_X);
        __half* wh = (__half*)(st + OFF_WH);

        // x tile: 130 cols x 32 ci (4 groups of 8 halves)
        #pragma unroll
        for (int i0 = 0; i0 < 3; i0++) {
            int i = tid + i0 * 256;
            if (i < 520) {
                int col = i >> 2, gi = i & 3;
                int gx = x0 + col - 1;
                __half* dst = xs + col * XT_STRIDE + gi * 8;
                if (yv && (unsigned)gx < (unsigned)WW)
                    cpasync16(dst, g_Xh + ((size_t)(yy * WW + gx) * C_IN + cic * 32 + gi * 8));
                else
                    sts_zero16(dst);
            }
        }
        // w tile: 128 co x 96 halves
        #pragma unroll
        for (int i0 = 0; i0 < 6; i0++) {
            int i = tid + i0 * 256;
            int co = i / 12, gi = i % 12;
            size_t o = (size_t)(coH * 128 + co) * KTOT + (kh * 4 + cic) * 96 + gi * 8;
            cpasync16(wh + co * WS_STRIDE + gi * 8, g_Wh + o);
        }
        CP_COMMIT();
    };

    load_chunk(0, sm);

    for (int c = 0; c < 12; c++) {
        char* cur = sm + (c & 1) * STAGE;
        if (c < 11) {
            load_chunk(c + 1, sm + ((c + 1) & 1) * STAGE);
            CP_WAIT(1);
        } else {
            CP_WAIT(0);
        }
        __syncthreads();

        const __half* xs = (const __half*)(cur + OFF_X);
        const __half* wh = (const __half*)(cur + OFF_WH);

        #pragma unroll
        for (int kw = 0; kw < 3; kw++) {
            #pragma unroll
            for (int ks = 0; ks < 2; ks++) {
                const int kb = kw * 32 + ks * 16;
                unsigned ah[2][4];
                #pragma unroll
                for (int mt = 0; mt < 2; mt++) {
                    int rowA = warp_co + mt * 16 + g;
                    const __half* ph = wh + rowA * WS_STRIDE + kb + 2 * r;
                    ah[mt][0] = *(const unsigned*)(ph);
                    ah[mt][1] = *(const unsigned*)(ph + 8 * WS_STRIDE);
                    ah[mt][2] = *(const unsigned*)(ph + 8);
                    ah[mt][3] = *(const unsigned*)(ph + 8 * WS_STRIDE + 8);
                }
                #pragma unroll
                for (int nt = 0; nt < 8; nt++) {
                    int col = warp_px + nt * 8 + g + kw;
                    const __half* pb = xs + col * XT_STRIDE + ks * 16 + 2 * r;
                    unsigned b[2];
                    b[0] = *(const unsigned*)(pb);
                    b[1] = *(const unsigned*)(pb + 8);
                    mma16816(d[0][nt], ah[0], b);
                    mma16816(d[1][nt], ah[1], b);
                }
            }
        }
        __syncthreads();   // all warps done with `cur` before refill
    }

    // ---- epilogue: bias + float2 stores ----
    #pragma unroll
    for (int mt = 0; mt < 2; mt++) {
        int co0 = coH * 128 + warp_co + mt * 16 + g;
        int co1 = co0 + 8;
        float b0 = bias[co0], b1 = bias[co1];
        float* row0 = out + (size_t)co0 * (HH * WW) + y * WW + x0;
        float* row1 = out + (size_t)co1 * (HH * WW) + y * WW + x0;
        #pragma unroll
        for (int nt = 0; nt < 8; nt++) {
            int px = warp_px + nt * 8 + 2 * r;
            *(float2*)(row0 + px) = make_float2(d[mt][nt][0] + b0, d[mt][nt][1] + b0);
            *(float2*)(row1 + px) = make_float2(d[mt][nt][2] + b1, d[mt][nt][3] + b1);
        }
    }
}

// ================= launcher =================
extern "C" void kernel_launch(void* const* d_in, const int* in_sizes, int n_in,
                              void* d_out, int out_size) {
    const float* x    = (const float*)d_in[0];
    const float* w    = (const float*)d_in[1];
    const float* bias = (const float*)d_in[2];
    float* out        = (float*)d_out;

    cudaFuncSetAttribute(conv_mma_kernel, cudaFuncAttributeMaxDynamicSharedMemorySize, SM_TOTAL);

    xprep_kernel<<<dim3(2, HH), 256>>>(x);
    wprep_kernel<<<C_OUT, 128>>>(w);
    conv_mma_kernel<<<dim3(2, HH, 2), 256, SM_TOTAL>>>(bias, out);
}